// round 11
// baseline (speedup 1.0000x reference)
#include <cuda_runtime.h>

// LUT tree, monomial form + layer-0 warp specialization.
// Warp j PERMANENTLY owns layer-0 node group j: its 32 nodes' monomial coefs
// live in registers for the whole kernel -> layer-0 does zero table loads.
// CTA tiles = 16 rows; per tile each warp evaluates its node column for all 16
// rows (LDG.128 -> 15 FMA -> STS.32), tail layers take 2 rows/warp from a
// double-buffered exchange; one __syncthreads per tile, tail(t-1) overlaps
// layer0(t). Depth-8 register ring prefetches x 8 rows ahead, crossing tile
// boundaries (CTA steals tiles two-deep so t+1 is known when its loads start).

#define THREADS  256
#define NWARPS   8
#define GRID     296            // 2 CTAs/SM * 148 SMs
#define RPT      16             // rows per CTA tile

#define NODE_F   20             // 16 coefs + 4 pad
#define N_NODES  341
#define TTOT     (N_NODES * NODE_F)      // 6820 floats
#define XBUF     (RPT * 256)             // 4096 floats per buffer
#define SMEM_B   ((TTOT + 2 * XBUF + 4) * 4)   // 60064 B

typedef unsigned uns;
__device__ uns g_ctr;
__global__ void reset_ctr() { g_ctr = 0; }

// eval with monomial coefs in registers; index = b0+2b1+4b2+8b3 (bit i <-> x_i)
__device__ __forceinline__ float node_eval_q(float4 q0, float4 q1, float4 q2,
                                             float4 q3, float4 xv) {
    float s0 = fmaf(xv.y, fmaf(xv.x, q0.w, q0.z), fmaf(xv.x, q0.y, q0.x));
    float s1 = fmaf(xv.y, fmaf(xv.x, q1.w, q1.z), fmaf(xv.x, q1.y, q1.x));
    float s2 = fmaf(xv.y, fmaf(xv.x, q2.w, q2.z), fmaf(xv.x, q2.y, q2.x));
    float s3 = fmaf(xv.y, fmaf(xv.x, q3.w, q3.z), fmaf(xv.x, q3.y, q3.x));
    return fmaf(xv.w, fmaf(xv.z, s3, s2), fmaf(xv.z, s1, s0));
}

__global__ void __launch_bounds__(THREADS, 2) lut_tree_kernel(
    const float* __restrict__ x,
    const float* __restrict__ t0, const float* __restrict__ t1,
    const float* __restrict__ t2, const float* __restrict__ t3,
    const float* __restrict__ t4,
    float* __restrict__ out, int nt)
{
    extern __shared__ __align__(16) float smem[];
    float* sh_t = smem;                 // [341][20] monomial coefs
    float* bufA = smem + TTOT;          // [16][256]
    float* bufB = bufA + XBUF;          // [16][256]
    uns*  sh_nx = (uns*)(bufB + XBUF);

    // ---- loader: Mobius-transform all tables into shared (padded) ----
    for (int g = threadIdx.x; g < N_NODES; g += THREADS) {
        const float* src; int ln;
        if (g < 256)      { src = t0; ln = g; }
        else if (g < 320) { src = t1; ln = g - 256; }
        else if (g < 336) { src = t2; ln = g - 320; }
        else if (g < 340) { src = t3; ln = g - 336; }
        else              { src = t4; ln = 0; }
        float v[16];
        #pragma unroll
        for (int k = 0; k < 16; ++k) v[k] = src[ln * 16 + k];
        #pragma unroll
        for (int i = 0; i < 4; ++i)
            #pragma unroll
            for (int c = 0; c < 16; ++c)
                if (c & (1 << i)) v[c] -= v[c ^ (1 << i)];
        float* dst = sh_t + g * NODE_F;
        #pragma unroll
        for (int k = 0; k < 16; ++k) dst[k] = v[k];
    }
    if (threadIdx.x == 0) {
        sh_nx[0] = atomicAdd(&g_ctr, 1);
        sh_nx[1] = atomicAdd(&g_ctr, 1);
    }
    __syncthreads();

    const int w    = threadIdx.x >> 5;
    const int lane = threadIdx.x & 31;
    const unsigned FULL = 0xffffffffu;

    uns t  = sh_nx[0];
    uns t1n = sh_nx[1];
    if (t >= (uns)nt) return;           // CTA-uniform

    // ---- persistent layer-0 table: node 32w+lane, 16 coefs in registers ----
    float4 tq0, tq1, tq2, tq3;
    {
        const float* cp = sh_t + (w * 32 + lane) * NODE_F;
        tq0 = *(const float4*)(cp + 0);
        tq1 = *(const float4*)(cp + 4);
        tq2 = *(const float4*)(cp + 8);
        tq3 = *(const float4*)(cp + 12);
    }

    const float4* xf = (const float4*)x;
    const int col = w * 32 + lane;      // this thread's float4 column

    // prologue: ring <- rows 0..7 of tile t
    float4 Rg[8];
    #pragma unroll
    for (int r = 0; r < 8; ++r)
        Rg[r] = xf[((size_t)t * RPT + r) * 256 + col];

    float* xb = bufA;                   // layer-0 write buffer
    float* xp = bufB;                   // tail read buffer (previous tile)
    uns prev = 0;
    int have_prev = 0;

    while (t < (uns)nt) {
        // ---- layer 0: 16 rows, zero table loads, ring prefetch 8 ahead ----
        #pragma unroll
        for (int r = 0; r < RPT; ++r) {
            float4 xv = Rg[r & 7];
            if (r < 8) {
                Rg[r & 7] = xf[((size_t)t * RPT + r + 8) * 256 + col];
            } else if (t1n < (uns)nt) {
                Rg[r & 7] = xf[((size_t)t1n * RPT + (r - 8)) * 256 + col];
            }
            xb[r * 256 + col] = node_eval_q(tq0, tq1, tq2, tq3, xv);
        }

        // ---- tail of previous tile: rows 2w, 2w+1 from xp ----
        if (have_prev) {
            float z0[2], z1[2], wv[2], vv[2];
            {   // layer 1, node 2*lane
                const float* cp = sh_t + (256 + 2 * lane) * NODE_F;
                float4 q0 = *(const float4*)(cp + 0), q1 = *(const float4*)(cp + 4);
                float4 q2 = *(const float4*)(cp + 8), q3 = *(const float4*)(cp + 12);
                #pragma unroll
                for (int i = 0; i < 2; ++i) {
                    float4 a = *(const float4*)&xp[(2 * w + i) * 256 + lane * 8];
                    z0[i] = node_eval_q(q0, q1, q2, q3, a);
                }
            }
            {   // layer 1, node 2*lane+1
                const float* cp = sh_t + (256 + 2 * lane + 1) * NODE_F;
                float4 q0 = *(const float4*)(cp + 0), q1 = *(const float4*)(cp + 4);
                float4 q2 = *(const float4*)(cp + 8), q3 = *(const float4*)(cp + 12);
                #pragma unroll
                for (int i = 0; i < 2; ++i) {
                    float4 a = *(const float4*)&xp[(2 * w + i) * 256 + lane * 8 + 4];
                    z1[i] = node_eval_q(q0, q1, q2, q3, a);
                }
            }
            {   // layer 2, node lane&15
                const float* cp = sh_t + (320 + (lane & 15)) * NODE_F;
                float4 q0 = *(const float4*)(cp + 0), q1 = *(const float4*)(cp + 4);
                float4 q2 = *(const float4*)(cp + 8), q3 = *(const float4*)(cp + 12);
                #pragma unroll
                for (int i = 0; i < 2; ++i) {
                    float4 b;
                    b.x = __shfl_sync(FULL, z0[i], (lane * 2) & 31);
                    b.y = __shfl_sync(FULL, z1[i], (lane * 2) & 31);
                    b.z = __shfl_sync(FULL, z0[i], (lane * 2 + 1) & 31);
                    b.w = __shfl_sync(FULL, z1[i], (lane * 2 + 1) & 31);
                    wv[i] = node_eval_q(q0, q1, q2, q3, b);
                }
            }
            {   // layer 3, node lane&3
                const float* cp = sh_t + (336 + (lane & 3)) * NODE_F;
                float4 q0 = *(const float4*)(cp + 0), q1 = *(const float4*)(cp + 4);
                float4 q2 = *(const float4*)(cp + 8), q3 = *(const float4*)(cp + 12);
                #pragma unroll
                for (int i = 0; i < 2; ++i) {
                    float4 c;
                    c.x = __shfl_sync(FULL, wv[i], (lane * 4 + 0) & 31);
                    c.y = __shfl_sync(FULL, wv[i], (lane * 4 + 1) & 31);
                    c.z = __shfl_sync(FULL, wv[i], (lane * 4 + 2) & 31);
                    c.w = __shfl_sync(FULL, wv[i], (lane * 4 + 3) & 31);
                    vv[i] = node_eval_q(q0, q1, q2, q3, c);
                }
            }
            {   // layer 4
                const float* cp = sh_t + 340 * NODE_F;
                float4 q0 = *(const float4*)(cp + 0), q1 = *(const float4*)(cp + 4);
                float4 q2 = *(const float4*)(cp + 8), q3 = *(const float4*)(cp + 12);
                #pragma unroll
                for (int i = 0; i < 2; ++i) {
                    float4 d;
                    d.x = __shfl_sync(FULL, vv[i], 0);
                    d.y = __shfl_sync(FULL, vv[i], 1);
                    d.z = __shfl_sync(FULL, vv[i], 2);
                    d.w = __shfl_sync(FULL, vv[i], 3);
                    if (lane == 0)
                        out[prev * RPT + 2 * w + i] =
                            node_eval_q(q0, q1, q2, q3, d);
                }
            }
        }

        if (threadIdx.x == 0) sh_nx[0] = atomicAdd(&g_ctr, 1);
        __syncthreads();                // xb complete CTA-wide; steal published

        prev = t; have_prev = 1;
        { float* tmp = xp; xp = xb; xb = tmp; }
        t = t1n;
        t1n = sh_nx[0];
    }

    // ---- drain: tail of the final tile ----
    {
        float z0[2], z1[2], wv[2], vv[2];
        {
            const float* cp = sh_t + (256 + 2 * lane) * NODE_F;
            float4 q0 = *(const float4*)(cp + 0), q1 = *(const float4*)(cp + 4);
            float4 q2 = *(const float4*)(cp + 8), q3 = *(const float4*)(cp + 12);
            #pragma unroll
            for (int i = 0; i < 2; ++i) {
                float4 a = *(const float4*)&xp[(2 * w + i) * 256 + lane * 8];
                z0[i] = node_eval_q(q0, q1, q2, q3, a);
            }
        }
        {
            const float* cp = sh_t + (256 + 2 * lane + 1) * NODE_F;
            float4 q0 = *(const float4*)(cp + 0), q1 = *(const float4*)(cp + 4);
            float4 q2 = *(const float4*)(cp + 8), q3 = *(const float4*)(cp + 12);
            #pragma unroll
            for (int i = 0; i < 2; ++i) {
                float4 a = *(const float4*)&xp[(2 * w + i) * 256 + lane * 8 + 4];
                z1[i] = node_eval_q(q0, q1, q2, q3, a);
            }
        }
        {
            const float* cp = sh_t + (320 + (lane & 15)) * NODE_F;
            float4 q0 = *(const float4*)(cp + 0), q1 = *(const float4*)(cp + 4);
            float4 q2 = *(const float4*)(cp + 8), q3 = *(const float4*)(cp + 12);
            #pragma unroll
            for (int i = 0; i < 2; ++i) {
                float4 b;
                b.x = __shfl_sync(FULL, z0[i], (lane * 2) & 31);
                b.y = __shfl_sync(FULL, z1[i], (lane * 2) & 31);
                b.z = __shfl_sync(FULL, z0[i], (lane * 2 + 1) & 31);
                b.w = __shfl_sync(FULL, z1[i], (lane * 2 + 1) & 31);
                wv[i] = node_eval_q(q0, q1, q2, q3, b);
            }
        }
        {
            const float* cp = sh_t + (336 + (lane & 3)) * NODE_F;
            float4 q0 = *(const float4*)(cp + 0), q1 = *(const float4*)(cp + 4);
            float4 q2 = *(const float4*)(cp + 8), q3 = *(const float4*)(cp + 12);
            #pragma unroll
            for (int i = 0; i < 2; ++i) {
                float4 c;
                c.x = __shfl_sync(FULL, wv[i], (lane * 4 + 0) & 31);
                c.y = __shfl_sync(FULL, wv[i], (lane * 4 + 1) & 31);
                c.z = __shfl_sync(FULL, wv[i], (lane * 4 + 2) & 31);
                c.w = __shfl_sync(FULL, wv[i], (lane * 4 + 3) & 31);
                vv[i] = node_eval_q(q0, q1, q2, q3, c);
            }
        }
        {
            const float* cp = sh_t + 340 * NODE_F;
            float4 q0 = *(const float4*)(cp + 0), q1 = *(const float4*)(cp + 4);
            float4 q2 = *(const float4*)(cp + 8), q3 = *(const float4*)(cp + 12);
            #pragma unroll
            for (int i = 0; i < 2; ++i) {
                float4 d;
                d.x = __shfl_sync(FULL, vv[i], 0);
                d.y = __shfl_sync(FULL, vv[i], 1);
                d.z = __shfl_sync(FULL, vv[i], 2);
                d.w = __shfl_sync(FULL, vv[i], 3);
                if (lane == 0)
                    out[prev * RPT + 2 * w + i] = node_eval_q(q0, q1, q2, q3, d);
            }
        }
    }
}

extern "C" void kernel_launch(void* const* d_in, const int* in_sizes, int n_in,
                              void* d_out, int out_size) {
    const float* x  = (const float*)d_in[0];
    const float* t0 = (const float*)d_in[1];
    const float* t1 = (const float*)d_in[2];
    const float* t2 = (const float*)d_in[3];
    const float* t3 = (const float*)d_in[4];
    const float* t4 = (const float*)d_in[5];
    float* out = (float*)d_out;

    int n_rows = in_sizes[0] / 1024;   // 32768
    int nt = n_rows / RPT;             // 2048 tiles

    reset_ctr<<<1, 1>>>();
    cudaFuncSetAttribute(lut_tree_kernel,
                         cudaFuncAttributeMaxDynamicSharedMemorySize, SMEM_B);
    lut_tree_kernel<<<GRID, THREADS, SMEM_B>>>(x, t0, t1, t2, t3, t4, out, nt);
}

// round 12
// speedup vs baseline: 1.0333x; 1.0333x over previous
#include <cuda_runtime.h>

// LUT tree, monomial-coefficient form (R10 base, prefetch distance 3).
// Loader Mobius-transforms tables -> node eval is 15 pure FMAs.
// Persistent warps steal 4-row tiles. Layer-0 x loads prefetched THREE batches
// ahead through the depth-4 register ring (slot (j+3)&3 was last read at j-1,
// so distance 3 is safe at depth 4; phase stable across tiles since 8%4==0).
// Next tile stolen at j==5; its batches 0..2 load under j=5..7 + tail layers.
// Tail layers are table-outer/rows-inner (coefs loaded once, reused over G=4).

#define THREADS  256
#define NWARPS   8
#define GRID     296            // 2 CTAs/SM * 148 SMs
#define G        4              // rows per tile

#define NODE_F   20             // 16 coefs + 4 pad -> 80B stride, conflict-free
#define N_NODES  341            // 256+64+16+4+1, by global node id g
#define TTOT     (N_NODES * NODE_F)
#define XCHF     (NWARPS * G * 256)
#define SMEM_B   ((TTOT + XCHF) * 4)   // 27280 + 32768 = 60048 B

typedef unsigned uns;
__device__ uns g_ctr;
__global__ void reset_ctr() { g_ctr = 0; }

// eval with monomial coefs in registers; index = b0+2b1+4b2+8b3 (bit i <-> x_i)
__device__ __forceinline__ float node_eval_q(float4 q0, float4 q1, float4 q2,
                                             float4 q3, float4 xv) {
    float s0 = fmaf(xv.y, fmaf(xv.x, q0.w, q0.z), fmaf(xv.x, q0.y, q0.x));
    float s1 = fmaf(xv.y, fmaf(xv.x, q1.w, q1.z), fmaf(xv.x, q1.y, q1.x));
    float s2 = fmaf(xv.y, fmaf(xv.x, q2.w, q2.z), fmaf(xv.x, q2.y, q2.x));
    float s3 = fmaf(xv.y, fmaf(xv.x, q3.w, q3.z), fmaf(xv.x, q3.y, q3.x));
    return fmaf(xv.w, fmaf(xv.z, s3, s2), fmaf(xv.z, s1, s0));
}

__device__ __forceinline__ void load_batch(float4* B, const float4* xb, int j, int lane) {
    #pragma unroll
    for (int r = 0; r < G; ++r)
        B[r] = xb[r * 256 + j * 32 + lane];
}

__global__ void __launch_bounds__(THREADS, 2) lut_tree_kernel(
    const float* __restrict__ x,
    const float* __restrict__ t0, const float* __restrict__ t1,
    const float* __restrict__ t2, const float* __restrict__ t3,
    const float* __restrict__ t4,
    float* __restrict__ out, int nt)
{
    extern __shared__ __align__(16) float smem[];
    float* sh_t = smem;                 // [341][20] monomial coefs
    float* sh_x = smem + TTOT;          // [NWARPS][G][256] exchange

    // ---- loader: fetch 16 corners per node, Mobius transform, store padded ----
    for (int g = threadIdx.x; g < N_NODES; g += THREADS) {
        const float* src; int ln;
        if (g < 256)      { src = t0; ln = g; }
        else if (g < 320) { src = t1; ln = g - 256; }
        else if (g < 336) { src = t2; ln = g - 320; }
        else if (g < 340) { src = t3; ln = g - 336; }
        else              { src = t4; ln = 0; }
        float v[16];
        #pragma unroll
        for (int k = 0; k < 16; ++k) v[k] = src[ln * 16 + k];
        #pragma unroll
        for (int i = 0; i < 4; ++i)
            #pragma unroll
            for (int c = 0; c < 16; ++c)
                if (c & (1 << i)) v[c] -= v[c ^ (1 << i)];
        float* dst = sh_t + g * NODE_F;
        #pragma unroll
        for (int k = 0; k < 16; ++k) dst[k] = v[k];
    }
    __syncthreads();

    const int warp = threadIdx.x >> 5;
    const int lane = threadIdx.x & 31;
    const unsigned FULL = 0xffffffffu;
    float* xch = sh_x + warp * (G * 256);

    uns t;
    if (lane == 0) t = atomicAdd(&g_ctr, 1);
    t = __shfl_sync(FULL, t, 0);

    float4 B[4][G];                      // ring: read B[j&3], write B[(j+3)&3]
    const float4* xb = (const float4*)x + (size_t)t * (G * 256);
    if (t < (uns)nt) {
        load_batch(B[0], xb, 0, lane);
        load_batch(B[1], xb, 1, lane);
        load_batch(B[2], xb, 2, lane);
    }

    while (t < (uns)nt) {
        uns tn = 0xffffffffu;
        const float4* xbn = xb;

        // ---- layer 0: prefetch distance 3, stream crosses into next tile ----
        #pragma unroll
        for (int j = 0; j < 8; ++j) {
            if (j < 5) {
                load_batch(B[(j + 3) & 3], xb, j + 3, lane);
            } else {
                if (j == 5) {
                    if (lane == 0) tn = atomicAdd(&g_ctr, 1);
                    tn = __shfl_sync(FULL, tn, 0);
                    xbn = (const float4*)x + (size_t)tn * (G * 256);
                }
                if (tn < (uns)nt)
                    load_batch(B[(j + 3) & 3], xbn, j - 5, lane);
            }
            const float* cp = sh_t + (j * 32 + lane) * NODE_F;
            float4 q0 = *(const float4*)(cp + 0);
            float4 q1 = *(const float4*)(cp + 4);
            float4 q2 = *(const float4*)(cp + 8);
            float4 q3 = *(const float4*)(cp + 12);
            #pragma unroll
            for (int r = 0; r < G; ++r)
                xch[r * 256 + j * 32 + lane] =
                    node_eval_q(q0, q1, q2, q3, B[j & 3][r]);
        }
        __syncwarp();

        // ---- layers 1..4, table-outer / rows-inner ----
        float z0[G], z1[G], wv[G], vv[G];

        {   // layer 1, node 2*lane
            const float* cp = sh_t + (256 + 2 * lane) * NODE_F;
            float4 q0 = *(const float4*)(cp + 0), q1 = *(const float4*)(cp + 4);
            float4 q2 = *(const float4*)(cp + 8), q3 = *(const float4*)(cp + 12);
            #pragma unroll
            for (int r = 0; r < G; ++r) {
                float4 a = *(const float4*)&xch[r * 256 + lane * 8];
                z0[r] = node_eval_q(q0, q1, q2, q3, a);
            }
        }
        {   // layer 1, node 2*lane+1
            const float* cp = sh_t + (256 + 2 * lane + 1) * NODE_F;
            float4 q0 = *(const float4*)(cp + 0), q1 = *(const float4*)(cp + 4);
            float4 q2 = *(const float4*)(cp + 8), q3 = *(const float4*)(cp + 12);
            #pragma unroll
            for (int r = 0; r < G; ++r) {
                float4 a = *(const float4*)&xch[r * 256 + lane * 8 + 4];
                z1[r] = node_eval_q(q0, q1, q2, q3, a);
            }
        }
        {   // layer 2, node lane&15
            const float* cp = sh_t + (320 + (lane & 15)) * NODE_F;
            float4 q0 = *(const float4*)(cp + 0), q1 = *(const float4*)(cp + 4);
            float4 q2 = *(const float4*)(cp + 8), q3 = *(const float4*)(cp + 12);
            #pragma unroll
            for (int r = 0; r < G; ++r) {
                float4 b;
                b.x = __shfl_sync(FULL, z0[r], (lane * 2) & 31);
                b.y = __shfl_sync(FULL, z1[r], (lane * 2) & 31);
                b.z = __shfl_sync(FULL, z0[r], (lane * 2 + 1) & 31);
                b.w = __shfl_sync(FULL, z1[r], (lane * 2 + 1) & 31);
                wv[r] = node_eval_q(q0, q1, q2, q3, b);
            }
        }
        {   // layer 3, node lane&3
            const float* cp = sh_t + (336 + (lane & 3)) * NODE_F;
            float4 q0 = *(const float4*)(cp + 0), q1 = *(const float4*)(cp + 4);
            float4 q2 = *(const float4*)(cp + 8), q3 = *(const float4*)(cp + 12);
            #pragma unroll
            for (int r = 0; r < G; ++r) {
                float4 c;
                c.x = __shfl_sync(FULL, wv[r], (lane * 4 + 0) & 31);
                c.y = __shfl_sync(FULL, wv[r], (lane * 4 + 1) & 31);
                c.z = __shfl_sync(FULL, wv[r], (lane * 4 + 2) & 31);
                c.w = __shfl_sync(FULL, wv[r], (lane * 4 + 3) & 31);
                vv[r] = node_eval_q(q0, q1, q2, q3, c);
            }
        }
        {   // layer 4, node 340
            const float* cp = sh_t + 340 * NODE_F;
            float4 q0 = *(const float4*)(cp + 0), q1 = *(const float4*)(cp + 4);
            float4 q2 = *(const float4*)(cp + 8), q3 = *(const float4*)(cp + 12);
            #pragma unroll
            for (int r = 0; r < G; ++r) {
                float4 d;
                d.x = __shfl_sync(FULL, vv[r], 0);
                d.y = __shfl_sync(FULL, vv[r], 1);
                d.z = __shfl_sync(FULL, vv[r], 2);
                d.w = __shfl_sync(FULL, vv[r], 3);
                if (lane == 0)
                    out[t * G + r] = node_eval_q(q0, q1, q2, q3, d);
            }
        }
        __syncwarp();

        t = tn;
        xb = xbn;
    }
}

extern "C" void kernel_launch(void* const* d_in, const int* in_sizes, int n_in,
                              void* d_out, int out_size) {
    const float* x  = (const float*)d_in[0];
    const float* t0 = (const float*)d_in[1];
    const float* t1 = (const float*)d_in[2];
    const float* t2 = (const float*)d_in[3];
    const float* t3 = (const float*)d_in[4];
    const float* t4 = (const float*)d_in[5];
    float* out = (float*)d_out;

    int n_rows = in_sizes[0] / 1024;       // 32768
    int nt = n_rows / G;                   // 8192 tiles

    reset_ctr<<<1, 1>>>();
    cudaFuncSetAttribute(lut_tree_kernel,
                         cudaFuncAttributeMaxDynamicSharedMemorySize, SMEM_B);
    lut_tree_kernel<<<GRID, THREADS, SMEM_B>>>(x, t0, t1, t2, t3, t4, out, nt);
}